// round 14
// baseline (speedup 1.0000x reference)
#include <cuda_runtime.h>

#define Bv 64
#define Tv 2048
#define Nv 128

__device__ __forceinline__ void ffma2(unsigned long long& d,
                                      unsigned long long a,
                                      unsigned long long b) {
    asm("fma.rn.f32x2 %0, %1, %2, %0;" : "+l"(d) : "l"(a), "l"(b));
}
__device__ __forceinline__ void fadd2(unsigned long long& d, unsigned long long a) {
    asm("add.rn.f32x2 %0, %0, %1;" : "+l"(d) : "l"(a));
}
__device__ __forceinline__ unsigned long long pack2(float a, float b) {
    unsigned long long r;
    asm("mov.b64 %0, {%1, %2};" : "=l"(r) : "f"(a), "f"(b));
    return r;
}
__device__ __forceinline__ float2 unpack2(unsigned long long v) {
    float2 r;
    asm("mov.b64 {%0, %1}, %2;" : "=f"(r.x), "=f"(r.y) : "l"(v));
    return r;
}
__device__ __forceinline__ float lo32(unsigned long long v) {
    float r;
    asm("{ .reg .f32 hi; mov.b64 {%0, hi}, %1; }" : "=f"(r) : "l"(v));
    return r;
}
// Group-local 128-thread named barriers with immediate ids.
__device__ __forceinline__ void bar1() {
    asm volatile("bar.sync 1, 128;" ::: "memory");
}
__device__ __forceinline__ void bar2() {
    asm volatile("bar.sync 2, 128;" ::: "memory");
}

// 128-tap packed dot product against smem vector Wp; also returns Wp[0].
__device__ __forceinline__ float dot128(const float* Wp,
                                        const unsigned long long (&e2)[Nv / 2],
                                        float& w0) {
    const ulonglong2* Wv = reinterpret_cast<const ulonglong2*>(Wp);
    ulonglong2 w = Wv[0];
    w0 = lo32(w.x);
    unsigned long long s0 = 0ull, s1 = 0ull, s2 = 0ull, s3 = 0ull;
    ffma2(s0, w.x, e2[0]);
    ffma2(s1, w.y, e2[1]);
    #pragma unroll
    for (int k = 1; k < Nv / 4; ++k) {
        w = Wv[k];
        if ((k & 1) == 0) { ffma2(s0, w.x, e2[2 * k]); ffma2(s1, w.y, e2[2 * k + 1]); }
        else              { ffma2(s2, w.x, e2[2 * k]); ffma2(s3, w.y, e2[2 * k + 1]); }
    }
    fadd2(s0, s1); fadd2(s2, s3); fadd2(s0, s2);
    float2 sp = unpack2(s0);
    return sp.x + sp.y;
}

// Exact power-of-2 rescale factor from w0's exponent; accumulates logM.
__device__ __forceinline__ float inv_scale(float w0, float& logM) {
    int ebits = __float_as_int(w0) & 0x7f800000;
    logM += (float)((ebits >> 23) - 127) * 0.693147180559945f;
    return __int_as_float(0x7f000000 - ebits);   // 2^(127 - E)
}

// One CTA per batch, 256 threads. Warps 0-3 run the FORWARD half-scan
// (alpha_0..alpha_mid), warps 4-7 the BACKWARD half-scan (beta_{len-1}..beta_mid),
// on independent named barriers so each SMSP interleaves two recurrence chains
// and hides one chain's barrier/LDS/dep stalls under the other's issue stream.
// In-CTA combine epilogue: out[b] = logMf + logMb + log(sum Wf*Wb).
__global__ __launch_bounds__(2 * Nv, 1)
void crf_bidir(const float* __restrict__ emissions,
               const int* __restrict__ token_sizes,
               const float* __restrict__ transitions,
               const float* __restrict__ head,
               const float* __restrict__ last,
               float* __restrict__ out)
{
    const int b   = blockIdx.x;
    const int tid = threadIdx.x;
    const int grp = tid >> 7;               // 0 = forward, 1 = backward
    const int n   = tid & (Nv - 1);         // tag index within group

    __shared__ __align__(16) float Wf[2][Nv];
    __shared__ __align__(16) float Wb[2][Nv];
    __shared__ float logMs[2];
    __shared__ float red[4];

    const int len = token_sizes[b];
    const int mid = len >> 1;
    const float* em = emissions + (size_t)b * Tv * Nv + n;

    // Packed E operands: forward = column n of exp(trans), backward = row n.
    unsigned long long e2[Nv / 2];
    if (grp == 0) {
        #pragma unroll
        for (int k = 0; k < Nv / 2; ++k)
            e2[k] = pack2(__expf(transitions[(2 * k + 0) * Nv + n]),
                          __expf(transitions[(2 * k + 1) * Nv + n]));
    } else {
        #pragma unroll
        for (int k = 0; k < Nv / 2; ++k)
            e2[k] = pack2(__expf(transitions[n * Nv + 2 * k + 0]),
                          __expf(transitions[n * Nv + 2 * k + 1]));
    }

    float logM;
    int p = 1;

    if (grp == 0) {
        // ---------------- forward: alpha_0 .. alpha_mid ----------------
        float a0 = head[n] + em[0];
        Wf[0][n] = a0;
        bar1();
        float K = Wf[0][0];
        logM = K;
        Wf[1][n] = __expf(a0 - K);
        bar1();

        float ex = __expf(em[Nv]);                    // exp(em_1)
        float nx = em[min(2, Tv - 1) * Nv];

        for (int t = 1; t <= mid; ++t) {
            float w0;
            float s = dot128(Wf[p], e2, w0);
            float m = ex * inv_scale(w0, logM);
            Wf[p ^ 1][n] = s * m;
            ex = __expf(nx);
            nx = em[min(t + 2, Tv - 1) * Nv];
            bar1();
            p ^= 1;
        }
        if (n == 0) logMs[0] = logM;
        if (p != 0) Wf[0][n] = Wf[1][n];              // canonicalize to Wf[0]
    } else {
        // ---------------- backward: beta_{len-1} .. beta_mid ----------------
        float b0 = last[n] + em[(size_t)(len - 1) * Nv];
        Wb[0][n] = b0;
        bar2();
        float K = Wb[0][0];
        logM = K;
        Wb[1][n] = __expf(b0 - K);
        bar2();

        float ex = __expf(em[(size_t)max(len - 2, 0) * Nv]);   // exp(em_{len-2})
        float nx = em[(size_t)max(len - 3, 0) * Nv];

        for (int t = len - 1; t > mid; --t) {
            float w0;
            float s = dot128(Wb[p], e2, w0);
            float exm = (t - 1 > mid) ? ex : 1.0f;    // final step: no emission factor
            float m = exm * inv_scale(w0, logM);
            Wb[p ^ 1][n] = s * m;
            ex = __expf(nx);
            nx = em[(size_t)max(t - 4, 0) * Nv];
            bar2();
            p ^= 1;
        }
        if (n == 0) logMs[1] = logM;
        if (p != 0) Wb[0][n] = Wb[1][n];              // canonicalize to Wb[0]
    }

    // ---------------- joint combine ----------------
    __syncthreads();
    if (tid < Nv) {
        float term = Wf[0][tid] * Wb[0][tid];
        #pragma unroll
        for (int o = 16; o > 0; o >>= 1)
            term += __shfl_down_sync(0xffffffffu, term, o);
        if ((tid & 31) == 0) red[tid >> 5] = term;
    }
    __syncthreads();
    if (tid == 0) {
        float tot = (red[0] + red[1]) + (red[2] + red[3]);
        out[b] = logMs[0] + logMs[1] + logf(tot);
    }
}

extern "C" void kernel_launch(void* const* d_in, const int* in_sizes, int n_in,
                              void* d_out, int out_size) {
    const float* emissions   = (const float*)d_in[0];
    const int*   token_sizes = (const int*)d_in[1];
    const float* transitions = (const float*)d_in[2];
    const float* head        = (const float*)d_in[3];
    const float* last        = (const float*)d_in[4];
    crf_bidir<<<Bv, 2 * Nv>>>(emissions, token_sizes, transitions, head, last,
                              (float*)d_out);
}